// round 8
// baseline (speedup 1.0000x reference)
#include <cuda_runtime.h>
#include <cuda_bf16.h>
#include <cstdint>

#define KDIM 4096
#define NDIM 11008
#define MMAX 8192
#define TM 256
#define TN 128
#define KC 64                 // int8 per K-chunk (64B row)
#define STAGES 4
#define ROWB 80               // padded row bytes
#define A_BYTES (TM * ROWB)   // 20480
#define B_BYTES (TN * ROWB)   // 10240
#define STAGE_BYTES (A_BYTES + B_BYTES)      // 30720
#define SMEM_TOTAL (STAGES * STAGE_BYTES)    // 122880
#define MAXC 256

// ---------------- scratch (static device globals) ---------------------------
__device__ float d_scale_col[NDIM];
__device__ float d_x_scale[MMAX];
__device__ int8_t d_qw[(size_t)NDIM * KDIM];
__device__ int8_t d_qx[(size_t)MMAX * KDIM];
__device__ float d_xout[(size_t)MAXC * MMAX];
__device__ float d_wout[(size_t)MAXC * NDIM];
__device__ int d_mask[KDIM];
__device__ int d_oidx[KDIM];
__device__ int d_ocnt;

// ---------------- PTX helpers ----------------------------------------------
__device__ __forceinline__ void cp_async16(void* smem, const void* gmem) {
    uint32_t a = (uint32_t)__cvta_generic_to_shared(smem);
    asm volatile("cp.async.cg.shared.global [%0], [%1], 16;\n" :: "r"(a), "l"(gmem));
}
__device__ __forceinline__ void cp_commit() { asm volatile("cp.async.commit_group;\n"); }
template <int N> __device__ __forceinline__ void cp_wait() {
    asm volatile("cp.async.wait_group %0;\n" :: "n"(N));
}
__device__ __forceinline__ void ldm_x4(uint32_t* r, const void* p) {
    uint32_t a = (uint32_t)__cvta_generic_to_shared(p);
    asm volatile("ldmatrix.sync.aligned.m8n8.x4.shared.b16 {%0,%1,%2,%3}, [%4];"
                 : "=r"(r[0]), "=r"(r[1]), "=r"(r[2]), "=r"(r[3]) : "r"(a));
}
__device__ __forceinline__ void mma_s8(int* c, const uint32_t* a, uint32_t b0, uint32_t b1) {
    asm volatile(
        "mma.sync.aligned.m16n8k32.row.col.s32.s8.s8.s32 "
        "{%0,%1,%2,%3}, {%4,%5,%6,%7}, {%8,%9}, {%0,%1,%2,%3};"
        : "+r"(c[0]), "+r"(c[1]), "+r"(c[2]), "+r"(c[3])
        : "r"(a[0]), "r"(a[1]), "r"(a[2]), "r"(a[3]), "r"(b0), "r"(b1));
}
__device__ __forceinline__ float block_max256(float v, float* sh) {
    int lane = threadIdx.x & 31, w = threadIdx.x >> 5;
#pragma unroll
    for (int o = 16; o; o >>= 1) v = fmaxf(v, __shfl_xor_sync(0xffffffffu, v, o));
    if (lane == 0) sh[w] = v;
    __syncthreads();
    if (w == 0) {
        v = (lane < 8) ? sh[lane] : 0.0f;
#pragma unroll
        for (int o = 4; o; o >>= 1) v = fmaxf(v, __shfl_xor_sync(0xffffffffu, v, o));
        if (lane == 0) sh[0] = v;
    }
    __syncthreads();
    v = sh[0];
    __syncthreads();
    return v;
}
__device__ __forceinline__ int q8(float x, float s) {
    return ((int)rintf(__fdiv_rn(x, s))) & 0xFF;
}
__device__ __forceinline__ int pack4(float4 v, float s) {
    return q8(v.x, s) | (q8(v.y, s) << 8) | (q8(v.z, s) << 16) | (q8(v.w, s) << 24);
}
// 16B-slot XOR swizzle within an 80B row (r,c in bytes; c in {0,16,32,48})
__device__ __forceinline__ uint32_t swz(int r, int c) {
    return (uint32_t)(r * ROWB + (c ^ ((((uint32_t)r >> 3) & 3) << 4)));
}

// ---------------- preprocessing --------------------------------------------
__global__ void zero_mask_kernel() {
    for (int k = threadIdx.x; k < KDIM; k += blockDim.x) d_mask[k] = 0;
}

__global__ __launch_bounds__(256) void find_outliers_kernel(const float* __restrict__ X,
                                                            const float* __restrict__ sigma,
                                                            int total4) {
    int i = blockIdx.x * 256 + threadIdx.x;
    if (i >= total4) return;
    float s = sigma[0];
    float4 v = reinterpret_cast<const float4*>(X)[i];
    int k = (i * 4) & (KDIM - 1);
    if (fabsf(v.x) > s) d_mask[k + 0] = 1;
    if (fabsf(v.y) > s) d_mask[k + 1] = 1;
    if (fabsf(v.z) > s) d_mask[k + 2] = 1;
    if (fabsf(v.w) > s) d_mask[k + 3] = 1;
}

__global__ void compact_kernel() {
    int lane = threadIdx.x;
    int base = 0;
    for (int it = 0; it < KDIM / 32; it++) {
        int k = it * 32 + lane;
        int p = (d_mask[k] != 0);
        unsigned bal = __ballot_sync(0xffffffffu, p);
        if (p) d_oidx[base + __popc(bal & ((1u << lane) - 1u))] = k;
        base += __popc(bal);
    }
    if (lane == 0) d_ocnt = base;
}

__global__ __launch_bounds__(256) void quant_w_kernel(const float* __restrict__ W) {
    __shared__ float sh[32];
    int n = blockIdx.x, tid = threadIdx.x;
    const float4* row = reinterpret_cast<const float4*>(W + (size_t)n * KDIM);
    float4 v[4];
    float amax = 0.0f;
#pragma unroll
    for (int i = 0; i < 4; i++) {
        v[i] = row[i * 256 + tid];
        amax = fmaxf(amax, fmaxf(fmaxf(fabsf(v[i].x), fabsf(v[i].y)),
                                 fmaxf(fabsf(v[i].z), fabsf(v[i].w))));
    }
    amax = block_max256(amax, sh);
    float scale = amax * (1.0f / 64.0f);
    if (tid == 0) d_scale_col[n] = scale;
    int* out = reinterpret_cast<int*>(d_qw + (size_t)n * KDIM);
#pragma unroll
    for (int i = 0; i < 4; i++) out[i * 256 + tid] = pack4(v[i], scale);
}

__global__ __launch_bounds__(256) void quant_x_kernel(const float* __restrict__ X) {
    __shared__ float sh[32];
    int m = blockIdx.x, tid = threadIdx.x;
    const float4* row = reinterpret_cast<const float4*>(X + (size_t)m * KDIM);
    const int4* mk4 = reinterpret_cast<const int4*>(d_mask);
    float4 v[4];
    int4 mk[4];
    float amax = 0.0f;
#pragma unroll
    for (int i = 0; i < 4; i++) {
        v[i] = row[i * 256 + tid];
        mk[i] = mk4[i * 256 + tid];
        if (mk[i].x) v[i].x = 0.0f;
        if (mk[i].y) v[i].y = 0.0f;
        if (mk[i].z) v[i].z = 0.0f;
        if (mk[i].w) v[i].w = 0.0f;
        amax = fmaxf(amax, fmaxf(fmaxf(fabsf(v[i].x), fabsf(v[i].y)),
                                 fmaxf(fabsf(v[i].z), fabsf(v[i].w))));
    }
    amax = block_max256(amax, sh);
    float xs = fmaxf(__fdiv_rn(amax, 127.0f), 1e-8f);
    if (tid == 0) d_x_scale[m] = xs;
    int* out = reinterpret_cast<int*>(d_qx + (size_t)m * KDIM);
#pragma unroll
    for (int i = 0; i < 4; i++) out[i * 256 + tid] = pack4(v[i], xs);
}

// coalesced-output gathers of outlier columns
__global__ __launch_bounds__(256) void gather_x_kernel(const float* __restrict__ X) {
    int m = blockIdx.x * 256 + threadIdx.x;
    int cnt = min(d_ocnt, MAXC);
    for (int c = 0; c < cnt; c++)
        d_xout[(size_t)c * MMAX + m] = X[(size_t)m * KDIM + d_oidx[c]];
}
__global__ __launch_bounds__(256) void gather_w_kernel() {
    int n = blockIdx.x * 256 + threadIdx.x;
    int cnt = min(d_ocnt, MAXC);
    for (int c = 0; c < cnt; c++)
        d_wout[(size_t)c * NDIM + n] = (float)d_qw[(size_t)n * KDIM + d_oidx[c]];
}

// ---------------- main GEMM: 256x128 tiles, s8 IMMA, 4-stage cp.async ------
__global__ __launch_bounds__(256) void gemm_kernel(float* __restrict__ Y) {
    extern __shared__ __align__(128) char smem[];
    const int tid = threadIdx.x, wid = tid >> 5, lane = tid & 31;
    const int wm = wid >> 1, wn = wid & 1;          // 4 x 2 warp grid
    const int m0 = blockIdx.y * TM, n0 = blockIdx.x * TN;

    const int8_t* gA = d_qx + (size_t)m0 * KDIM;
    const int8_t* gB = d_qw + (size_t)n0 * KDIM;

    int acc[4][8][4];
#pragma unroll
    for (int a = 0; a < 4; a++)
#pragma unroll
        for (int b = 0; b < 8; b++)
#pragma unroll
            for (int c = 0; c < 4; c++) acc[a][b][c] = 0;

    const int br = tid & 127, bc = (tid >> 7) * 32;

    auto load_stage = [&](int s, int kk) {
        char* base = smem + s * STAGE_BYTES;
#pragma unroll
        for (int i = 0; i < 4; i++)
            cp_async16(base + swz(tid, i * 16), gA + (size_t)tid * KDIM + kk + i * 16);
        char* baseB = base + A_BYTES;
#pragma unroll
        for (int j = 0; j < 2; j++)
            cp_async16(baseB + swz(br, bc + j * 16), gB + (size_t)br * KDIM + kk + bc + j * 16);
        cp_commit();
    };

    load_stage(0, 0);
    load_stage(1, KC);
    load_stage(2, 2 * KC);

    const int T = KDIM / KC;   // 64
    for (int t = 0; t < T; t++) {
        cp_wait<2>();
        __syncthreads();
        if (t + 3 < T) load_stage((t + 3) & 3, (t + 3) * KC);
        const char* baseA = smem + (t & 3) * STAGE_BYTES;
        const char* baseB = baseA + A_BYTES;
#pragma unroll
        for (int ks = 0; ks < 2; ks++) {
            uint32_t af[4][4], bfr[4][4];
#pragma unroll
            for (int mt = 0; mt < 4; mt++) {
                int r = wm * 64 + mt * 16 + (lane & 15);
                int c = ks * 32 + ((lane >> 4) << 4);
                ldm_x4(af[mt], baseA + swz(r, c));
            }
#pragma unroll
            for (int np = 0; np < 4; np++) {
                int r = wn * 64 + np * 16 + ((lane >> 4) << 3) + (lane & 7);
                int c = ks * 32 + (((lane >> 3) & 1) << 4);
                ldm_x4(bfr[np], baseB + swz(r, c));
            }
#pragma unroll
            for (int mt = 0; mt < 4; mt++)
#pragma unroll
                for (int nt = 0; nt < 8; nt++)
                    mma_s8(acc[mt][nt], af[mt],
                           bfr[nt >> 1][(nt & 1) * 2], bfr[nt >> 1][(nt & 1) * 2 + 1]);
        }
        __syncthreads();
    }
    cp_wait<0>();
    __syncthreads();

    // ---------------- epilogue ---------------------------------------------
    float* xcol = reinterpret_cast<float*>(smem);
    float* wcol = xcol + 256;
    float* scs = wcol + 128;
    if (tid < 128) scs[tid] = d_scale_col[n0 + tid];
    __syncthreads();

    const int g = lane >> 2, q = lane & 3;
    float xs0[4], xs1[4];
#pragma unroll
    for (int mt = 0; mt < 4; mt++) {
        int r = m0 + wm * 64 + mt * 16 + g;
        xs0[mt] = d_x_scale[r];
        xs1[mt] = d_x_scale[r + 8];
    }

    // in-place int32 -> fp32 conversion with per-row scale
    float* fa = reinterpret_cast<float*>(acc);
#pragma unroll
    for (int mt = 0; mt < 4; mt++)
#pragma unroll
        for (int nt = 0; nt < 8; nt++) {
            int idx = (mt * 8 + nt) * 4;
            float t0 = (float)acc[mt][nt][0] * xs0[mt];
            float t1 = (float)acc[mt][nt][1] * xs0[mt];
            float t2 = (float)acc[mt][nt][2] * xs1[mt];
            float t3 = (float)acc[mt][nt][3] * xs1[mt];
            fa[idx + 0] = t0; fa[idx + 1] = t1; fa[idx + 2] = t2; fa[idx + 3] = t3;
        }

    // fp32 outlier rank-C correction (coalesced staged loads)
    const int cnt = min(d_ocnt, MAXC);
    for (int c = 0; c < cnt; c++) {
        __syncthreads();
        xcol[tid] = d_xout[(size_t)c * MMAX + m0 + tid];
        if (tid < 128) wcol[tid] = d_wout[(size_t)c * NDIM + n0 + tid];
        __syncthreads();
        float xv0[4], xv1[4];
#pragma unroll
        for (int mt = 0; mt < 4; mt++) {
            xv0[mt] = xcol[wm * 64 + mt * 16 + g];
            xv1[mt] = xcol[wm * 64 + mt * 16 + 8 + g];
        }
#pragma unroll
        for (int nt = 0; nt < 8; nt++) {
            float wv0 = wcol[wn * 64 + nt * 8 + q * 2];
            float wv1 = wcol[wn * 64 + nt * 8 + q * 2 + 1];
            int idx = nt * 4;
#pragma unroll
            for (int mt = 0; mt < 4; mt++) {
                fa[mt * 32 + idx + 0] += xv0[mt] * wv0;
                fa[mt * 32 + idx + 1] += xv0[mt] * wv1;
                fa[mt * 32 + idx + 2] += xv1[mt] * wv0;
                fa[mt * 32 + idx + 3] += xv1[mt] * wv1;
            }
        }
    }

    // per-col weight scale + store
#pragma unroll
    for (int mt = 0; mt < 4; mt++) {
        int m1 = m0 + wm * 64 + mt * 16 + g;
#pragma unroll
        for (int nt = 0; nt < 8; nt++) {
            int nl = wn * 64 + nt * 8 + q * 2;
            float sc0 = scs[nl], sc1 = scs[nl + 1];
            int idx = (mt * 8 + nt) * 4;
            float2 r0 = make_float2(fa[idx + 0] * sc0, fa[idx + 1] * sc1);
            float2 r1 = make_float2(fa[idx + 2] * sc0, fa[idx + 3] * sc1);
            *reinterpret_cast<float2*>(&Y[(size_t)m1 * NDIM + n0 + nl]) = r0;
            *reinterpret_cast<float2*>(&Y[(size_t)(m1 + 8) * NDIM + n0 + nl]) = r1;
        }
    }
}

// ---------------- launcher --------------------------------------------------
extern "C" void kernel_launch(void* const* d_in, const int* in_sizes, int n_in,
                              void* d_out, int out_size) {
    const float* x   = (const float*)d_in[0];
    const float* w   = (const float*)d_in[1];
    const float* sig = (const float*)d_in[2];
    float* y = (float*)d_out;

    const int M = in_sizes[0] / KDIM;   // 8192
    (void)n_in; (void)out_size;

    cudaFuncSetAttribute(gemm_kernel, cudaFuncAttributeMaxDynamicSharedMemorySize,
                         SMEM_TOTAL);

    zero_mask_kernel<<<1, 256>>>();
    {
        int total4 = M * KDIM / 4;
        find_outliers_kernel<<<(total4 + 255) / 256, 256>>>(x, sig, total4);
    }
    compact_kernel<<<1, 32>>>();
    quant_w_kernel<<<NDIM, 256>>>(w);
    quant_x_kernel<<<M, 256>>>(x);
    gather_x_kernel<<<M / 256, 256>>>(x);
    gather_w_kernel<<<NDIM / 256, 256>>>();

    dim3 grid(NDIM / TN, M / TM);
    gemm_kernel<<<grid, 256, SMEM_TOTAL>>>(y);
}

// round 10
// speedup vs baseline: 1.6165x; 1.6165x over previous
#include <cuda_runtime.h>
#include <cuda_bf16.h>
#include <cstdint>

#define KDIM 4096
#define NDIM 11008
#define MMAX 8192
#define TM 128
#define TN 256
#define KC 64                  // bf16 per K-chunk = 128B row
#define STAGES 4
#define ROWB 128
#define A_BYTES (TM * ROWB)    // 16384
#define B_BYTES (TN * ROWB)    // 32768
#define STAGE_BYTES (A_BYTES + B_BYTES)   // 49152
#define SMEM_TOTAL (STAGES * STAGE_BYTES) // 196608
#define MAXC 256

// ---------------- scratch (static device globals) ---------------------------
__device__ float d_scale_col[NDIM];
__device__ float d_x_scale[MMAX];
__device__ __nv_bfloat16 d_qw[(size_t)NDIM * KDIM];
__device__ __nv_bfloat16 d_qx[(size_t)MMAX * KDIM];
__device__ float d_xout[(size_t)MAXC * MMAX];
__device__ float d_wout[(size_t)MAXC * NDIM];
__device__ int d_mask[KDIM];
__device__ int d_oidx[KDIM];
__device__ int d_ocnt;

// ---------------- PTX helpers ----------------------------------------------
__device__ __forceinline__ void cp_async16(void* smem, const void* gmem) {
    uint32_t a = (uint32_t)__cvta_generic_to_shared(smem);
    asm volatile("cp.async.cg.shared.global [%0], [%1], 16;\n" :: "r"(a), "l"(gmem));
}
__device__ __forceinline__ void cp_commit() { asm volatile("cp.async.commit_group;\n"); }
template <int N> __device__ __forceinline__ void cp_wait() {
    asm volatile("cp.async.wait_group %0;\n" :: "n"(N));
}
__device__ __forceinline__ void ldm_x4(uint32_t* r, const void* p) {
    uint32_t a = (uint32_t)__cvta_generic_to_shared(p);
    asm volatile("ldmatrix.sync.aligned.m8n8.x4.shared.b16 {%0,%1,%2,%3}, [%4];"
                 : "=r"(r[0]), "=r"(r[1]), "=r"(r[2]), "=r"(r[3]) : "r"(a));
}
__device__ __forceinline__ void mma_bf16(float* c, const uint32_t* a, uint32_t b0, uint32_t b1) {
    asm volatile(
        "mma.sync.aligned.m16n8k16.row.col.f32.bf16.bf16.f32 "
        "{%0,%1,%2,%3}, {%4,%5,%6,%7}, {%8,%9}, {%0,%1,%2,%3};"
        : "+f"(c[0]), "+f"(c[1]), "+f"(c[2]), "+f"(c[3])
        : "r"(a[0]), "r"(a[1]), "r"(a[2]), "r"(a[3]), "r"(b0), "r"(b1));
}
__device__ __forceinline__ float block_max256(float v, float* sh) {
    int lane = threadIdx.x & 31, w = threadIdx.x >> 5;
#pragma unroll
    for (int o = 16; o; o >>= 1) v = fmaxf(v, __shfl_xor_sync(0xffffffffu, v, o));
    if (lane == 0) sh[w] = v;
    __syncthreads();
    if (w == 0) {
        v = (lane < 8) ? sh[lane] : 0.0f;
#pragma unroll
        for (int o = 4; o; o >>= 1) v = fmaxf(v, __shfl_xor_sync(0xffffffffu, v, o));
        if (lane == 0) sh[0] = v;
    }
    __syncthreads();
    v = sh[0];
    __syncthreads();
    return v;
}
__device__ __forceinline__ unsigned short qb(float x, float s) {
    return __bfloat16_as_ushort(__float2bfloat16_rn(rintf(__fdiv_rn(x, s))));
}
// swizzle: 16B-slot XOR within a 128B row; cb must be 16B-aligned
__device__ __forceinline__ uint32_t sw(int r, int cb) {
    return (uint32_t)(r * ROWB + (cb ^ ((r & 7) << 4)));
}

// ---------------- preprocessing --------------------------------------------
__global__ void zero_mask_kernel() {
    for (int k = threadIdx.x; k < KDIM; k += blockDim.x) d_mask[k] = 0;
}

__global__ __launch_bounds__(256) void find_outliers_kernel(const float* __restrict__ X,
                                                            const float* __restrict__ sigma,
                                                            int total4) {
    int i = blockIdx.x * 256 + threadIdx.x;
    if (i >= total4) return;
    float s = sigma[0];
    float4 v = reinterpret_cast<const float4*>(X)[i];
    int k = (i * 4) & (KDIM - 1);
    if (fabsf(v.x) > s) d_mask[k + 0] = 1;
    if (fabsf(v.y) > s) d_mask[k + 1] = 1;
    if (fabsf(v.z) > s) d_mask[k + 2] = 1;
    if (fabsf(v.w) > s) d_mask[k + 3] = 1;
}

__global__ void compact_kernel() {
    int lane = threadIdx.x;
    int base = 0;
    for (int it = 0; it < KDIM / 32; it++) {
        int k = it * 32 + lane;
        int p = (d_mask[k] != 0);
        unsigned bal = __ballot_sync(0xffffffffu, p);
        if (p) d_oidx[base + __popc(bal & ((1u << lane) - 1u))] = k;
        base += __popc(bal);
    }
    if (lane == 0) d_ocnt = base;
}

__global__ __launch_bounds__(256) void quant_w_kernel(const float* __restrict__ W) {
    __shared__ float sh[32];
    int n = blockIdx.x, tid = threadIdx.x;
    const float4* row = reinterpret_cast<const float4*>(W + (size_t)n * KDIM);
    float4 v[4];
    float amax = 0.0f;
#pragma unroll
    for (int i = 0; i < 4; i++) {
        v[i] = row[i * 256 + tid];
        amax = fmaxf(amax, fmaxf(fmaxf(fabsf(v[i].x), fabsf(v[i].y)),
                                 fmaxf(fabsf(v[i].z), fabsf(v[i].w))));
    }
    amax = block_max256(amax, sh);
    float scale = amax * (1.0f / 64.0f);
    if (tid == 0) d_scale_col[n] = scale;
    ushort4* out = reinterpret_cast<ushort4*>(d_qw + (size_t)n * KDIM);
#pragma unroll
    for (int i = 0; i < 4; i++) {
        ushort4 u;
        u.x = qb(v[i].x, scale); u.y = qb(v[i].y, scale);
        u.z = qb(v[i].z, scale); u.w = qb(v[i].w, scale);
        out[i * 256 + tid] = u;
    }
}

__global__ __launch_bounds__(256) void quant_x_kernel(const float* __restrict__ X) {
    __shared__ float sh[32];
    int m = blockIdx.x, tid = threadIdx.x;
    const float4* row = reinterpret_cast<const float4*>(X + (size_t)m * KDIM);
    const int4* mk4 = reinterpret_cast<const int4*>(d_mask);
    float4 v[4];
    int4 mk[4];
    float amax = 0.0f;
#pragma unroll
    for (int i = 0; i < 4; i++) {
        v[i] = row[i * 256 + tid];
        mk[i] = mk4[i * 256 + tid];
        if (mk[i].x) v[i].x = 0.0f;
        if (mk[i].y) v[i].y = 0.0f;
        if (mk[i].z) v[i].z = 0.0f;
        if (mk[i].w) v[i].w = 0.0f;
        amax = fmaxf(amax, fmaxf(fmaxf(fabsf(v[i].x), fabsf(v[i].y)),
                                 fmaxf(fabsf(v[i].z), fabsf(v[i].w))));
    }
    amax = block_max256(amax, sh);
    float xs = fmaxf(__fdiv_rn(amax, 127.0f), 1e-8f);
    if (tid == 0) d_x_scale[m] = xs;
    ushort4* out = reinterpret_cast<ushort4*>(d_qx + (size_t)m * KDIM);
#pragma unroll
    for (int i = 0; i < 4; i++) {
        ushort4 u;
        u.x = qb(v[i].x, xs); u.y = qb(v[i].y, xs);
        u.z = qb(v[i].z, xs); u.w = qb(v[i].w, xs);
        out[i * 256 + tid] = u;
    }
}

// coalesced-output gathers of outlier columns
__global__ __launch_bounds__(256) void gather_x_kernel(const float* __restrict__ X) {
    int m = blockIdx.x * 256 + threadIdx.x;
    int cnt = min(d_ocnt, MAXC);
    for (int c = 0; c < cnt; c++)
        d_xout[(size_t)c * MMAX + m] = X[(size_t)m * KDIM + d_oidx[c]];
}
__global__ __launch_bounds__(256) void gather_w_kernel() {
    int n = blockIdx.x * 256 + threadIdx.x;
    int cnt = min(d_ocnt, MAXC);
    for (int c = 0; c < cnt; c++)
        d_wout[(size_t)c * NDIM + n] = __bfloat162float(d_qw[(size_t)n * KDIM + d_oidx[c]]);
}

// ---------- main GEMM: 128x256 tile, bf16 HMMA, KC=64, 4-stage cp.async ----
__global__ __launch_bounds__(512) void gemm_kernel(float* __restrict__ Y) {
    extern __shared__ __align__(128) char smem[];
    const int tid = threadIdx.x, wid = tid >> 5, lane = tid & 31;
    const int wm = wid >> 3, wn = wid & 7;          // 2 x 8 warp grid, 64x32 tiles
    const int m0 = blockIdx.y * TM, n0 = blockIdx.x * TN;

    const char* gA = (const char*)(d_qx + (size_t)m0 * KDIM);
    const char* gB = (const char*)(d_qw + (size_t)n0 * KDIM);
    const size_t GROW = (size_t)KDIM * 2;   // gmem row bytes

    float acc[4][4][4];
#pragma unroll
    for (int a = 0; a < 4; a++)
#pragma unroll
        for (int b = 0; b < 4; b++)
#pragma unroll
            for (int c = 0; c < 4; c++) acc[a][b][c] = 0.0f;

    const int ar = tid & 127, ab = (tid >> 7) * 32;    // A: 2 slots of 16B
    const int br = tid & 255, bb = (tid >> 8) * 64;    // B: 4 slots of 16B

    auto load_stage = [&](int s, int kkB) {   // kkB = K offset in BYTES
        char* base = smem + s * STAGE_BYTES;
#pragma unroll
        for (int i = 0; i < 2; i++)
            cp_async16(base + sw(ar, ab + i * 16), gA + (size_t)ar * GROW + kkB + ab + i * 16);
        char* baseB = base + A_BYTES;
#pragma unroll
        for (int i = 0; i < 4; i++)
            cp_async16(baseB + sw(br, bb + i * 16), gB + (size_t)br * GROW + kkB + bb + i * 16);
        cp_commit();
    };

    load_stage(0, 0);
    load_stage(1, KC * 2);
    load_stage(2, 2 * KC * 2);

    // ldmatrix address components (R1-proven patterns; byte columns)
    const int aRow = lane & 15, aCb = (lane >> 4) << 4;
    const int bRow = ((lane >> 4) << 3) + (lane & 7), bCb = ((lane >> 3) & 1) << 4;

    const int T = KDIM / KC;   // 64
    for (int t = 0; t < T; t++) {
        cp_wait<2>();
        __syncthreads();
        if (t + 3 < T) load_stage((t + 3) & 3, (t + 3) * KC * 2);
        else cp_commit();      // empty group keeps wait_group accounting exact
        const char* bA = smem + (t & 3) * STAGE_BYTES;
        const char* bB = bA + A_BYTES;
#pragma unroll
        for (int ks = 0; ks < 4; ks++) {      // 4 x k16
            uint32_t af[4][4], bfr[2][4];
#pragma unroll
            for (int mt = 0; mt < 4; mt++)
                ldm_x4(af[mt], bA + sw(wm * 64 + mt * 16 + aRow, ks * 32 + aCb));
#pragma unroll
            for (int np = 0; np < 2; np++)
                ldm_x4(bfr[np], bB + sw(wn * 32 + np * 16 + bRow, ks * 32 + bCb));
#pragma unroll
            for (int mt = 0; mt < 4; mt++)
#pragma unroll
                for (int nt = 0; nt < 4; nt++)
                    mma_bf16(acc[mt][nt], af[mt],
                             bfr[nt >> 1][(nt & 1) * 2], bfr[nt >> 1][(nt & 1) * 2 + 1]);
        }
    }
    cp_wait<0>();
    __syncthreads();

    // ---------------- epilogue ---------------------------------------------
    float* xcol = reinterpret_cast<float*>(smem);          // 128
    float* wcol = xcol + 128;                              // 256
    float* scs = wcol + 256;                               // 256
    if (tid < 256) scs[tid] = d_scale_col[n0 + tid];
    __syncthreads();

    const int g = lane >> 2, q = lane & 3;
    float xs0[4], xs1[4];
#pragma unroll
    for (int mt = 0; mt < 4; mt++) {
        int r = m0 + wm * 64 + mt * 16 + g;
        xs0[mt] = d_x_scale[r];
        xs1[mt] = d_x_scale[r + 8];
    }
#pragma unroll
    for (int mt = 0; mt < 4; mt++)
#pragma unroll
        for (int nt = 0; nt < 4; nt++) {
            acc[mt][nt][0] *= xs0[mt]; acc[mt][nt][1] *= xs0[mt];
            acc[mt][nt][2] *= xs1[mt]; acc[mt][nt][3] *= xs1[mt];
        }

    // fp32 outlier rank-C correction (coalesced staged loads)
    const int cnt = min(d_ocnt, MAXC);
    for (int c = 0; c < cnt; c++) {
        __syncthreads();
        if (tid < 128) xcol[tid] = d_xout[(size_t)c * MMAX + m0 + tid];
        else if (tid < 384) wcol[tid - 128] = d_wout[(size_t)c * NDIM + n0 + tid - 128];
        __syncthreads();
        float xv0[4], xv1[4];
#pragma unroll
        for (int mt = 0; mt < 4; mt++) {
            xv0[mt] = xcol[wm * 64 + mt * 16 + g];
            xv1[mt] = xcol[wm * 64 + mt * 16 + 8 + g];
        }
#pragma unroll
        for (int nt = 0; nt < 4; nt++) {
            float wv0 = wcol[wn * 32 + nt * 8 + q * 2];
            float wv1 = wcol[wn * 32 + nt * 8 + q * 2 + 1];
#pragma unroll
            for (int mt = 0; mt < 4; mt++) {
                acc[mt][nt][0] += xv0[mt] * wv0;
                acc[mt][nt][1] += xv0[mt] * wv1;
                acc[mt][nt][2] += xv1[mt] * wv0;
                acc[mt][nt][3] += xv1[mt] * wv1;
            }
        }
    }

    // per-col weight scale + store
#pragma unroll
    for (int mt = 0; mt < 4; mt++) {
        int m1 = m0 + wm * 64 + mt * 16 + g;
#pragma unroll
        for (int nt = 0; nt < 4; nt++) {
            int nl = wn * 32 + nt * 8 + q * 2;
            float sc0 = scs[nl], sc1 = scs[nl + 1];
            float2 r0 = make_float2(acc[mt][nt][0] * sc0, acc[mt][nt][1] * sc1);
            float2 r1 = make_float2(acc[mt][nt][2] * sc0, acc[mt][nt][3] * sc1);
            *reinterpret_cast<float2*>(&Y[(size_t)m1 * NDIM + n0 + nl]) = r0;
            *reinterpret_cast<float2*>(&Y[(size_t)(m1 + 8) * NDIM + n0 + nl]) = r1;
        }
    }
}

// ---------------- launcher --------------------------------------------------
extern "C" void kernel_launch(void* const* d_in, const int* in_sizes, int n_in,
                              void* d_out, int out_size) {
    const float* x   = (const float*)d_in[0];
    const float* w   = (const float*)d_in[1];
    const float* sig = (const float*)d_in[2];
    float* y = (float*)d_out;

    const int M = in_sizes[0] / KDIM;   // 8192
    (void)n_in; (void)out_size;

    cudaFuncSetAttribute(gemm_kernel, cudaFuncAttributeMaxDynamicSharedMemorySize,
                         SMEM_TOTAL);

    zero_mask_kernel<<<1, 256>>>();
    {
        int total4 = M * KDIM / 4;
        find_outliers_kernel<<<(total4 + 255) / 256, 256>>>(x, sig, total4);
    }
    compact_kernel<<<1, 32>>>();
    quant_w_kernel<<<NDIM, 256>>>(w);
    quant_x_kernel<<<M, 256>>>(x);
    gather_x_kernel<<<M / 256, 256>>>(x);
    gather_w_kernel<<<NDIM / 256, 256>>>();

    dim3 grid(NDIM / TN, M / TM);
    gemm_kernel<<<grid, 512, SMEM_TOTAL>>>(y);
}

// round 13
// speedup vs baseline: 2.3407x; 1.4480x over previous
#include <cuda_runtime.h>
#include <cuda_bf16.h>
#include <cstdint>

#define KDIM 4096
#define NDIM 11008
#define MMAX 8192
#define MAXC 256
#define TT 128                 // K iterations (KDIM/32)

// ---------------- scratch (static device globals) ---------------------------
__device__ float d_scale_col[NDIM];
__device__ float d_x_scale[MMAX];
__device__ __nv_bfloat16 d_qw[(size_t)NDIM * KDIM];
__device__ __nv_bfloat16 d_qx[(size_t)MMAX * KDIM];
__device__ float d_xout[(size_t)MAXC * MMAX];
__device__ float d_wout[(size_t)MAXC * NDIM];
__device__ int d_mask[KDIM];
__device__ int d_oidx[KDIM];
__device__ int d_ocnt;

// ---------------- PTX helpers ----------------------------------------------
__device__ __forceinline__ void cp_async16(uint32_t smem, const void* gmem) {
    asm volatile("cp.async.cg.shared.global [%0], [%1], 16;\n" :: "r"(smem), "l"(gmem));
}
__device__ __forceinline__ void cp_commit() { asm volatile("cp.async.commit_group;\n"); }
template <int N> __device__ __forceinline__ void cp_wait() {
    asm volatile("cp.async.wait_group %0;\n" :: "n"(N));
}
__device__ __forceinline__ void ldm_x4(uint32_t* r, const void* p) {
    uint32_t a = (uint32_t)__cvta_generic_to_shared(p);
    asm volatile("ldmatrix.sync.aligned.m8n8.x4.shared.b16 {%0,%1,%2,%3}, [%4];"
                 : "=r"(r[0]), "=r"(r[1]), "=r"(r[2]), "=r"(r[3]) : "r"(a));
}
__device__ __forceinline__ void mma_bf16(float* c, const uint32_t* a, uint32_t b0, uint32_t b1) {
    asm volatile(
        "mma.sync.aligned.m16n8k16.row.col.f32.bf16.bf16.f32 "
        "{%0,%1,%2,%3}, {%4,%5,%6,%7}, {%8,%9}, {%0,%1,%2,%3};"
        : "+f"(c[0]), "+f"(c[1]), "+f"(c[2]), "+f"(c[3])
        : "r"(a[0]), "r"(a[1]), "r"(a[2]), "r"(a[3]), "r"(b0), "r"(b1));
}
__device__ __forceinline__ float block_max256(float v, float* sh) {
    int lane = threadIdx.x & 31, w = threadIdx.x >> 5;
#pragma unroll
    for (int o = 16; o; o >>= 1) v = fmaxf(v, __shfl_xor_sync(0xffffffffu, v, o));
    if (lane == 0) sh[w] = v;
    __syncthreads();
    if (w == 0) {
        v = (lane < 8) ? sh[lane] : 0.0f;
#pragma unroll
        for (int o = 4; o; o >>= 1) v = fmaxf(v, __shfl_xor_sync(0xffffffffu, v, o));
        if (lane == 0) sh[0] = v;
    }
    __syncthreads();
    v = sh[0];
    __syncthreads();
    return v;
}
__device__ __forceinline__ unsigned short qb(float x, float s) {
    return __bfloat16_as_ushort(__float2bfloat16_rn(rintf(__fdiv_rn(x, s))));
}

// ---------------- preprocessing --------------------------------------------
__global__ void zero_mask_kernel() {
    for (int k = threadIdx.x; k < KDIM; k += blockDim.x) d_mask[k] = 0;
}

__global__ __launch_bounds__(256) void find_outliers_kernel(const float* __restrict__ X,
                                                            const float* __restrict__ sigma,
                                                            int total4) {
    int i = blockIdx.x * 256 + threadIdx.x;
    if (i >= total4) return;
    float s = sigma[0];
    float4 v = reinterpret_cast<const float4*>(X)[i];
    int k = (i * 4) & (KDIM - 1);
    if (fabsf(v.x) > s) d_mask[k + 0] = 1;
    if (fabsf(v.y) > s) d_mask[k + 1] = 1;
    if (fabsf(v.z) > s) d_mask[k + 2] = 1;
    if (fabsf(v.w) > s) d_mask[k + 3] = 1;
}

__global__ void compact_kernel() {
    int lane = threadIdx.x;
    int base = 0;
    for (int it = 0; it < KDIM / 32; it++) {
        int k = it * 32 + lane;
        int p = (d_mask[k] != 0);
        unsigned bal = __ballot_sync(0xffffffffu, p);
        if (p) d_oidx[base + __popc(bal & ((1u << lane) - 1u))] = k;
        base += __popc(bal);
    }
    if (lane == 0) d_ocnt = base;
}

// quantize W row + fused outlier-column gather (d_wout)
__global__ __launch_bounds__(256) void quant_w_kernel(const float* __restrict__ W) {
    __shared__ float sh[32];
    int n = blockIdx.x, tid = threadIdx.x;
    const float4* row = reinterpret_cast<const float4*>(W + (size_t)n * KDIM);
    float4 v[4];
    float amax = 0.0f;
#pragma unroll
    for (int i = 0; i < 4; i++) {
        v[i] = row[i * 256 + tid];
        amax = fmaxf(amax, fmaxf(fmaxf(fabsf(v[i].x), fabsf(v[i].y)),
                                 fmaxf(fabsf(v[i].z), fabsf(v[i].w))));
    }
    amax = block_max256(amax, sh);
    float scale = amax * (1.0f / 64.0f);
    if (tid == 0) d_scale_col[n] = scale;
    ushort4* out = reinterpret_cast<ushort4*>(d_qw + (size_t)n * KDIM);
#pragma unroll
    for (int i = 0; i < 4; i++) {
        ushort4 u;
        u.x = qb(v[i].x, scale); u.y = qb(v[i].y, scale);
        u.z = qb(v[i].z, scale); u.w = qb(v[i].w, scale);
        out[i * 256 + tid] = u;
    }
    int cnt = min(d_ocnt, MAXC);
    if (tid < cnt) {
        float wv = W[(size_t)n * KDIM + d_oidx[tid]];
        d_wout[(size_t)tid * NDIM + n] = rintf(__fdiv_rn(wv, scale));
    }
}

// quantize X row (mask outliers) + fused outlier gather (d_xout)
__global__ __launch_bounds__(256) void quant_x_kernel(const float* __restrict__ X) {
    __shared__ float sh[32];
    int m = blockIdx.x, tid = threadIdx.x;
    const float4* row = reinterpret_cast<const float4*>(X + (size_t)m * KDIM);
    const int4* mk4 = reinterpret_cast<const int4*>(d_mask);
    float4 v[4];
    int4 mk[4];
    float amax = 0.0f;
#pragma unroll
    for (int i = 0; i < 4; i++) {
        v[i] = row[i * 256 + tid];
        mk[i] = mk4[i * 256 + tid];
        if (mk[i].x) v[i].x = 0.0f;
        if (mk[i].y) v[i].y = 0.0f;
        if (mk[i].z) v[i].z = 0.0f;
        if (mk[i].w) v[i].w = 0.0f;
        amax = fmaxf(amax, fmaxf(fmaxf(fabsf(v[i].x), fabsf(v[i].y)),
                                 fmaxf(fabsf(v[i].z), fabsf(v[i].w))));
    }
    amax = block_max256(amax, sh);
    float xs = fmaxf(__fdiv_rn(amax, 127.0f), 1e-8f);
    if (tid == 0) d_x_scale[m] = xs;
    ushort4* out = reinterpret_cast<ushort4*>(d_qx + (size_t)m * KDIM);
#pragma unroll
    for (int i = 0; i < 4; i++) {
        ushort4 u;
        u.x = qb(v[i].x, xs); u.y = qb(v[i].y, xs);
        u.z = qb(v[i].z, xs); u.w = qb(v[i].w, xs);
        out[i * 256 + tid] = u;
    }
    int cnt = min(d_ocnt, MAXC);
    if (tid < cnt)
        d_xout[(size_t)tid * MMAX + m] = X[(size_t)m * KDIM + d_oidx[tid]];
}

// ---- main GEMM: 128x128 tile, bf16 HMMA, 3-stage ring, 1 sync/iter --------
__global__ __launch_bounds__(256) void gemm_kernel(float* __restrict__ Y) {
    __shared__ __align__(16) __nv_bfloat16 sA[3][128][40];
    __shared__ __align__(16) __nv_bfloat16 sB[3][128][40];

    const int tid = threadIdx.x;
    const int lane = tid & 31, wid = tid >> 5;
    const int wm = wid >> 2, wn = wid & 3;             // 2 x 4 warp grid
    const int m0 = blockIdx.y * 128, n0 = blockIdx.x * 128;

    const __nv_bfloat16* gA = d_qx + (size_t)m0 * KDIM;
    const __nv_bfloat16* gB = d_qw + (size_t)n0 * KDIM;

    const int lrow = tid >> 2;             // 0..63
    const int lcol = (tid & 3) << 3;       // 0,8,16,24 (bf16 units)

    float acc[4][4][4];
#pragma unroll
    for (int a = 0; a < 4; a++)
#pragma unroll
        for (int b = 0; b < 4; b++)
#pragma unroll
            for (int c = 0; c < 4; c++) acc[a][b][c] = 0.0f;

    // ldmatrix address patterns (R1-proven)
    const int aRow = lane & 15;
    const int aCol = (lane >> 4) << 3;
    const int bRow = ((lane >> 4) << 3) + (lane & 7);
    const int bCol = ((lane >> 3) & 1) << 3;

    auto load_stage = [&](int buf, int kk) {
#pragma unroll
        for (int r = 0; r < 2; r++) {
            int row = lrow + r * 64;
            cp_async16((uint32_t)__cvta_generic_to_shared(&sA[buf][row][lcol]),
                       gA + (size_t)row * KDIM + kk + lcol);
            cp_async16((uint32_t)__cvta_generic_to_shared(&sB[buf][row][lcol]),
                       gB + (size_t)row * KDIM + kk + lcol);
        }
        cp_commit();
    };

    load_stage(0, 0);
    load_stage(1, 32);

    // 3-stage ring, single barrier per iteration:
    // write target (t+2)%3 == buffer read at t-1, fenced by this barrier.
    for (int t = 0; t < TT; t++) {
        if (t == TT - 1) cp_wait<0>(); else cp_wait<1>();
        __syncthreads();
        if (t + 2 < TT) load_stage((t + 2) % 3, (t + 2) * 32);
        const int buf = t % 3;
#pragma unroll
        for (int ks = 0; ks < 2; ks++) {
            uint32_t af[4][4], bfr[2][4];
#pragma unroll
            for (int mt = 0; mt < 4; mt++)
                ldm_x4(af[mt], &sA[buf][wm * 64 + mt * 16 + aRow][ks * 16 + aCol]);
#pragma unroll
            for (int np = 0; np < 2; np++)
                ldm_x4(bfr[np], &sB[buf][wn * 32 + np * 16 + bRow][ks * 16 + bCol]);
#pragma unroll
            for (int mt = 0; mt < 4; mt++)
#pragma unroll
                for (int nt = 0; nt < 4; nt++)
                    mma_bf16(acc[mt][nt], af[mt],
                             bfr[nt >> 1][(nt & 1) * 2], bfr[nt >> 1][(nt & 1) * 2 + 1]);
        }
    }
    __syncthreads();   // all reads done before smem reuse below

    // ---------------- epilogue ---------------------------------------------
    float* xcol = reinterpret_cast<float*>(&sA[0][0][0]);   // 128
    float* wcol = xcol + 128;                               // 128
    float* scs = wcol + 128;                                // 128
    if (tid < 128) scs[tid] = d_scale_col[n0 + tid];
    __syncthreads();

    const int g = lane >> 2, q = lane & 3;
    float xs0[4], xs1[4];
#pragma unroll
    for (int mt = 0; mt < 4; mt++) {
        int mr = m0 + wm * 64 + mt * 16 + g;
        xs0[mt] = d_x_scale[mr];
        xs1[mt] = d_x_scale[mr + 8];
    }
#pragma unroll
    for (int mt = 0; mt < 4; mt++)
#pragma unroll
        for (int nt = 0; nt < 4; nt++) {
            acc[mt][nt][0] *= xs0[mt]; acc[mt][nt][1] *= xs0[mt];
            acc[mt][nt][2] *= xs1[mt]; acc[mt][nt][3] *= xs1[mt];
        }

    // fp32 outlier rank-C correction (coalesced pre-gathered buffers)
    const int cnt = min(d_ocnt, MAXC);
    for (int c = 0; c < cnt; c++) {
        __syncthreads();
        if (tid < 128) xcol[tid] = d_xout[(size_t)c * MMAX + m0 + tid];
        else xcol[tid] = d_wout[(size_t)c * NDIM + n0 + tid - 128];  // wcol == xcol+128
        __syncthreads();
        float xv0[4], xv1[4], wv0[4], wv1[4];
#pragma unroll
        for (int mt = 0; mt < 4; mt++) {
            xv0[mt] = xcol[wm * 64 + mt * 16 + g];
            xv1[mt] = xcol[wm * 64 + mt * 16 + 8 + g];
        }
#pragma unroll
        for (int nt = 0; nt < 4; nt++) {
            wv0[nt] = wcol[wn * 32 + nt * 8 + q * 2];
            wv1[nt] = wcol[wn * 32 + nt * 8 + q * 2 + 1];
        }
#pragma unroll
        for (int mt = 0; mt < 4; mt++)
#pragma unroll
            for (int nt = 0; nt < 4; nt++) {
                acc[mt][nt][0] += xv0[mt] * wv0[nt];
                acc[mt][nt][1] += xv0[mt] * wv1[nt];
                acc[mt][nt][2] += xv1[mt] * wv0[nt];
                acc[mt][nt][3] += xv1[mt] * wv1[nt];
            }
    }

    // per-col weight scale + store
#pragma unroll
    for (int mt = 0; mt < 4; mt++) {
        int m1 = m0 + wm * 64 + mt * 16 + g;
#pragma unroll
        for (int nt = 0; nt < 4; nt++) {
            int nl = wn * 32 + nt * 8 + q * 2;
            float sc0 = scs[nl], sc1 = scs[nl + 1];
            float2 r0 = make_float2(acc[mt][nt][0] * sc0, acc[mt][nt][1] * sc1);
            float2 r1 = make_float2(acc[mt][nt][2] * sc0, acc[mt][nt][3] * sc1);
            *reinterpret_cast<float2*>(&Y[(size_t)m1 * NDIM + n0 + nl]) = r0;
            *reinterpret_cast<float2*>(&Y[(size_t)(m1 + 8) * NDIM + n0 + nl]) = r1;
        }
    }
}

// ---------------- launcher --------------------------------------------------
extern "C" void kernel_launch(void* const* d_in, const int* in_sizes, int n_in,
                              void* d_out, int out_size) {
    const float* x   = (const float*)d_in[0];
    const float* w   = (const float*)d_in[1];
    const float* sig = (const float*)d_in[2];
    float* y = (float*)d_out;

    const int M = in_sizes[0] / KDIM;   // 8192
    (void)n_in; (void)out_size;

    zero_mask_kernel<<<1, 256>>>();
    {
        int total4 = M * KDIM / 4;
        find_outliers_kernel<<<(total4 + 255) / 256, 256>>>(x, sig, total4);
    }
    compact_kernel<<<1, 32>>>();
    quant_w_kernel<<<NDIM, 256>>>(w);
    quant_x_kernel<<<M, 256>>>(x);

    dim3 grid(NDIM / 128, M / 128);
    gemm_kernel<<<grid, 256>>>(y);
}

// round 17
// speedup vs baseline: 2.4903x; 1.0639x over previous
#include <cuda_runtime.h>
#include <cuda_bf16.h>
#include <cstdint>

#define KDIM 4096
#define NDIM 11008
#define MMAX 8192
#define MAXC 256
#define TT 128                 // K iterations (KDIM/32)

// ---------------- scratch (static device globals) ---------------------------
__device__ float d_scale_col[NDIM];
__device__ float d_x_scale[MMAX];
__device__ __nv_bfloat16 d_qw[(size_t)NDIM * KDIM];
__device__ __nv_bfloat16 d_qx[(size_t)MMAX * KDIM];
__device__ float d_xout[(size_t)MAXC * MMAX];
__device__ float d_wout[(size_t)MAXC * NDIM];
__device__ int d_mask[KDIM];
__device__ int d_oidx[KDIM];
__device__ int d_ocnt;

// ---------------- PTX helpers ----------------------------------------------
__device__ __forceinline__ void cp_async16(uint32_t smem, const void* gmem) {
    asm volatile("cp.async.cg.shared.global [%0], [%1], 16;\n" :: "r"(smem), "l"(gmem));
}
__device__ __forceinline__ void cp_commit() { asm volatile("cp.async.commit_group;\n"); }
template <int N> __device__ __forceinline__ void cp_wait() {
    asm volatile("cp.async.wait_group %0;\n" :: "n"(N));
}
__device__ __forceinline__ void ldm_x4(uint32_t* r, const void* p) {
    uint32_t a = (uint32_t)__cvta_generic_to_shared(p);
    asm volatile("ldmatrix.sync.aligned.m8n8.x4.shared.b16 {%0,%1,%2,%3}, [%4];"
                 : "=r"(r[0]), "=r"(r[1]), "=r"(r[2]), "=r"(r[3]) : "r"(a));
}
__device__ __forceinline__ void mma_bf16(float* c, const uint32_t* a, uint32_t b0, uint32_t b1) {
    asm volatile(
        "mma.sync.aligned.m16n8k16.row.col.f32.bf16.bf16.f32 "
        "{%0,%1,%2,%3}, {%4,%5,%6,%7}, {%8,%9}, {%0,%1,%2,%3};"
        : "+f"(c[0]), "+f"(c[1]), "+f"(c[2]), "+f"(c[3])
        : "r"(a[0]), "r"(a[1]), "r"(a[2]), "r"(a[3]), "r"(b0), "r"(b1));
}
__device__ __forceinline__ float block_max256(float v, float* sh) {
    int lane = threadIdx.x & 31, w = threadIdx.x >> 5;
#pragma unroll
    for (int o = 16; o; o >>= 1) v = fmaxf(v, __shfl_xor_sync(0xffffffffu, v, o));
    if (lane == 0) sh[w] = v;
    __syncthreads();
    if (w == 0) {
        v = (lane < 8) ? sh[lane] : 0.0f;
#pragma unroll
        for (int o = 4; o; o >>= 1) v = fmaxf(v, __shfl_xor_sync(0xffffffffu, v, o));
        if (lane == 0) sh[0] = v;
    }
    __syncthreads();
    v = sh[0];
    __syncthreads();
    return v;
}
__device__ __forceinline__ unsigned short qb(float x, float s) {
    return __bfloat16_as_ushort(__float2bfloat16_rn(rintf(__fdiv_rn(x, s))));
}

// ---------------- preprocessing --------------------------------------------
__global__ void zero_mask_kernel() {
    for (int k = threadIdx.x; k < KDIM; k += blockDim.x) d_mask[k] = 0;
}

__global__ __launch_bounds__(256) void find_outliers_kernel(const float* __restrict__ X,
                                                            const float* __restrict__ sigma,
                                                            int total4) {
    int i = blockIdx.x * 256 + threadIdx.x;
    if (i >= total4) return;
    float s = sigma[0];
    float4 v = reinterpret_cast<const float4*>(X)[i];
    int k = (i * 4) & (KDIM - 1);
    if (fabsf(v.x) > s) d_mask[k + 0] = 1;
    if (fabsf(v.y) > s) d_mask[k + 1] = 1;
    if (fabsf(v.z) > s) d_mask[k + 2] = 1;
    if (fabsf(v.w) > s) d_mask[k + 3] = 1;
}

__global__ void compact_kernel() {
    int lane = threadIdx.x;
    int base = 0;
    for (int it = 0; it < KDIM / 32; it++) {
        int k = it * 32 + lane;
        int p = (d_mask[k] != 0);
        unsigned bal = __ballot_sync(0xffffffffu, p);
        if (p) d_oidx[base + __popc(bal & ((1u << lane) - 1u))] = k;
        base += __popc(bal);
    }
    if (lane == 0) d_ocnt = base;
}

// quantize W row + fused outlier-column gather (d_wout)
__global__ __launch_bounds__(256) void quant_w_kernel(const float* __restrict__ W) {
    __shared__ float sh[32];
    int n = blockIdx.x, tid = threadIdx.x;
    const float4* row = reinterpret_cast<const float4*>(W + (size_t)n * KDIM);
    float4 v[4];
    float amax = 0.0f;
#pragma unroll
    for (int i = 0; i < 4; i++) {
        v[i] = row[i * 256 + tid];
        amax = fmaxf(amax, fmaxf(fmaxf(fabsf(v[i].x), fabsf(v[i].y)),
                                 fmaxf(fabsf(v[i].z), fabsf(v[i].w))));
    }
    amax = block_max256(amax, sh);
    float scale = amax * (1.0f / 64.0f);
    if (tid == 0) d_scale_col[n] = scale;
    ushort4* out = reinterpret_cast<ushort4*>(d_qw + (size_t)n * KDIM);
#pragma unroll
    for (int i = 0; i < 4; i++) {
        ushort4 u;
        u.x = qb(v[i].x, scale); u.y = qb(v[i].y, scale);
        u.z = qb(v[i].z, scale); u.w = qb(v[i].w, scale);
        out[i * 256 + tid] = u;
    }
    int cnt = min(d_ocnt, MAXC);
    if (tid < cnt) {
        float wv = W[(size_t)n * KDIM + d_oidx[tid]];
        d_wout[(size_t)tid * NDIM + n] = rintf(__fdiv_rn(wv, scale));
    }
}

// quantize X row (mask outliers) + fused outlier gather (d_xout)
__global__ __launch_bounds__(256) void quant_x_kernel(const float* __restrict__ X) {
    __shared__ float sh[32];
    int m = blockIdx.x, tid = threadIdx.x;
    const float4* row = reinterpret_cast<const float4*>(X + (size_t)m * KDIM);
    const int4* mk4 = reinterpret_cast<const int4*>(d_mask);
    float4 v[4];
    int4 mk[4];
    float amax = 0.0f;
#pragma unroll
    for (int i = 0; i < 4; i++) {
        v[i] = row[i * 256 + tid];
        mk[i] = mk4[i * 256 + tid];
        if (mk[i].x) v[i].x = 0.0f;
        if (mk[i].y) v[i].y = 0.0f;
        if (mk[i].z) v[i].z = 0.0f;
        if (mk[i].w) v[i].w = 0.0f;
        amax = fmaxf(amax, fmaxf(fmaxf(fabsf(v[i].x), fabsf(v[i].y)),
                                 fmaxf(fabsf(v[i].z), fabsf(v[i].w))));
    }
    amax = block_max256(amax, sh);
    float xs = fmaxf(__fdiv_rn(amax, 127.0f), 1e-8f);
    if (tid == 0) d_x_scale[m] = xs;
    ushort4* out = reinterpret_cast<ushort4*>(d_qx + (size_t)m * KDIM);
#pragma unroll
    for (int i = 0; i < 4; i++) {
        ushort4 u;
        u.x = qb(v[i].x, xs); u.y = qb(v[i].y, xs);
        u.z = qb(v[i].z, xs); u.w = qb(v[i].w, xs);
        out[i * 256 + tid] = u;
    }
    int cnt = min(d_ocnt, MAXC);
    if (tid < cnt)
        d_xout[(size_t)tid * MMAX + m] = X[(size_t)m * KDIM + d_oidx[tid]];
}

// ---- main GEMM: 128x128 tile, bf16 HMMA, 4-stage ring, 1 sync per K64 -----
__global__ __launch_bounds__(256) void gemm_kernel(float* __restrict__ Y) {
    __shared__ __align__(16) __nv_bfloat16 sA[4][128][40];
    __shared__ __align__(16) __nv_bfloat16 sB[4][128][40];

    const int tid = threadIdx.x;
    const int lane = tid & 31, wid = tid >> 5;
    const int wm = wid >> 2, wn = wid & 3;             // 2 x 4 warp grid
    const int m0 = blockIdx.y * 128, n0 = blockIdx.x * 128;

    const __nv_bfloat16* gA = d_qx + (size_t)m0 * KDIM;
    const __nv_bfloat16* gB = d_qw + (size_t)n0 * KDIM;

    const int lrow = tid >> 2;             // 0..63
    const int lcol = (tid & 3) << 3;       // 0,8,16,24 (bf16 units)

    float acc[4][4][4];
#pragma unroll
    for (int a = 0; a < 4; a++)
#pragma unroll
        for (int b = 0; b < 4; b++)
#pragma unroll
            for (int c = 0; c < 4; c++) acc[a][b][c] = 0.0f;

    // ldmatrix address patterns (R1-proven)
    const int aRow = lane & 15;
    const int aCol = (lane >> 4) << 3;
    const int bRow = ((lane >> 4) << 3) + (lane & 7);
    const int bCol = ((lane >> 3) & 1) << 3;

    auto load_stage = [&](int buf, int kk) {
#pragma unroll
        for (int r = 0; r < 2; r++) {
            int row = lrow + r * 64;
            cp_async16((uint32_t)__cvta_generic_to_shared(&sA[buf][row][lcol]),
                       gA + (size_t)row * KDIM + kk + lcol);
            cp_async16((uint32_t)__cvta_generic_to_shared(&sB[buf][row][lcol]),
                       gB + (size_t)row * KDIM + kk + lcol);
        }
        cp_commit();
    };

    load_stage(0, 0);
    load_stage(1, 32);

    // 4-stage ring, one barrier per K64 pair. Pair tt reads buffers 2tt,2tt+1
    // and writes 2tt+2,2tt+3 == the buffers read in pair tt-1, fenced by the
    // pair's top barrier.
    for (int tt = 0; tt < TT / 2; tt++) {
        cp_wait<0>();
        __syncthreads();
        const int t2 = 2 * tt + 2, t3 = 2 * tt + 3;
        if (t2 < TT) load_stage(t2 & 3, t2 * 32);
        if (t3 < TT) load_stage(t3 & 3, t3 * 32);
#pragma unroll
        for (int h = 0; h < 2; h++) {
            const int buf = (2 * tt + h) & 3;
#pragma unroll
            for (int ks = 0; ks < 2; ks++) {
                uint32_t af[4][4], bfr[2][4];
#pragma unroll
                for (int mt = 0; mt < 4; mt++)
                    ldm_x4(af[mt], &sA[buf][wm * 64 + mt * 16 + aRow][ks * 16 + aCol]);
#pragma unroll
                for (int np = 0; np < 2; np++)
                    ldm_x4(bfr[np], &sB[buf][wn * 32 + np * 16 + bRow][ks * 16 + bCol]);
#pragma unroll
                for (int mt = 0; mt < 4; mt++)
#pragma unroll
                    for (int nt = 0; nt < 4; nt++)
                        mma_bf16(acc[mt][nt], af[mt],
                                 bfr[nt >> 1][(nt & 1) * 2], bfr[nt >> 1][(nt & 1) * 2 + 1]);
            }
        }
    }
    __syncthreads();   // all reads done before smem reuse below

    // ---------------- epilogue ---------------------------------------------
    float* x0 = reinterpret_cast<float*>(&sA[0][0][0]);   // 128
    float* w0 = x0 + 128;                                 // 128
    float* x1 = w0 + 128;                                 // 128
    float* w1 = x1 + 128;                                 // 128
    float* scs = w1 + 128;                                // 128
    if (tid < 128) scs[tid] = d_scale_col[n0 + tid];
    __syncthreads();

    const int g = lane >> 2, q = lane & 3;
    float xs0[4], xs1[4];
#pragma unroll
    for (int mt = 0; mt < 4; mt++) {
        int mr = m0 + wm * 64 + mt * 16 + g;
        xs0[mt] = d_x_scale[mr];
        xs1[mt] = d_x_scale[mr + 8];
    }
#pragma unroll
    for (int mt = 0; mt < 4; mt++)
#pragma unroll
        for (int nt = 0; nt < 4; nt++) {
            acc[mt][nt][0] *= xs0[mt]; acc[mt][nt][1] *= xs0[mt];
            acc[mt][nt][2] *= xs1[mt]; acc[mt][nt][3] *= xs1[mt];
        }

    // fp32 outlier rank-C correction, two columns per barrier pair
    const int cnt = min(d_ocnt, MAXC);
    for (int c = 0; c < cnt; c += 2) {
        __syncthreads();
        if (tid < 128) x0[tid] = d_xout[(size_t)c * MMAX + m0 + tid];
        else w0[tid - 128] = d_wout[(size_t)c * NDIM + n0 + tid - 128];
        if (c + 1 < cnt) {
            if (tid < 128) x1[tid] = d_xout[(size_t)(c + 1) * MMAX + m0 + tid];
            else w1[tid - 128] = d_wout[(size_t)(c + 1) * NDIM + n0 + tid - 128];
        }
        __syncthreads();
#pragma unroll
        for (int u = 0; u < 2; u++) {
            if (u == 1 && c + 1 >= cnt) break;
            const float* xc = (u == 0) ? x0 : x1;
            const float* wc = (u == 0) ? w0 : w1;
            float xv0[4], xv1[4], wv0[4], wv1[4];
#pragma unroll
            for (int mt = 0; mt < 4; mt++) {
                xv0[mt] = xc[wm * 64 + mt * 16 + g];
                xv1[mt] = xc[wm * 64 + mt * 16 + 8 + g];
            }
#pragma unroll
            for (int nt = 0; nt < 4; nt++) {
                wv0[nt] = wc[wn * 32 + nt * 8 + q * 2];
                wv1[nt] = wc[wn * 32 + nt * 8 + q * 2 + 1];
            }
#pragma unroll
            for (int mt = 0; mt < 4; mt++)
#pragma unroll
                for (int nt = 0; nt < 4; nt++) {
                    acc[mt][nt][0] += xv0[mt] * wv0[nt];
                    acc[mt][nt][1] += xv0[mt] * wv1[nt];
                    acc[mt][nt][2] += xv1[mt] * wv0[nt];
                    acc[mt][nt][3] += xv1[mt] * wv1[nt];
                }
        }
    }

    // per-col weight scale + store
#pragma unroll
    for (int mt = 0; mt < 4; mt++) {
        int m1 = m0 + wm * 64 + mt * 16 + g;
#pragma unroll
        for (int nt = 0; nt < 4; nt++) {
            int nl = wn * 32 + nt * 8 + q * 2;
            float sc0 = scs[nl], sc1 = scs[nl + 1];
            float2 r0 = make_float2(acc[mt][nt][0] * sc0, acc[mt][nt][1] * sc1);
            float2 r1 = make_float2(acc[mt][nt][2] * sc0, acc[mt][nt][3] * sc1);
            *reinterpret_cast<float2*>(&Y[(size_t)m1 * NDIM + n0 + nl]) = r0;
            *reinterpret_cast<float2*>(&Y[(size_t)(m1 + 8) * NDIM + n0 + nl]) = r1;
        }
    }
}

// ---------------- launcher --------------------------------------------------
extern "C" void kernel_launch(void* const* d_in, const int* in_sizes, int n_in,
                              void* d_out, int out_size) {
    const float* x   = (const float*)d_in[0];
    const float* w   = (const float*)d_in[1];
    const float* sig = (const float*)d_in[2];
    float* y = (float*)d_out;

    const int M = in_sizes[0] / KDIM;   // 8192
    (void)n_in; (void)out_size;

    zero_mask_kernel<<<1, 256>>>();
    {
        int total4 = M * KDIM / 4;
        find_outliers_kernel<<<(total4 + 255) / 256, 256>>>(x, sig, total4);
    }
    compact_kernel<<<1, 32>>>();
    quant_w_kernel<<<NDIM, 256>>>(w);
    quant_x_kernel<<<M, 256>>>(x);

    dim3 grid(NDIM / 128, M / 128);
    gemm_kernel<<<grid, 256>>>(y);
}